// round 10
// baseline (speedup 1.0000x reference)
#include <cuda_runtime.h>

// ---------------- problem constants ----------------
#define PP        0.075f
#define HH        1440
#define WW        1440
#define GZ        32
#define GT        10
#define VZ        0.25f
#define VT        0.05f
#define ZCENTER   4.0f
#define TZCENTER  5.0f
#define CC        64

#define HWC       (HH*WW)                 // 2,073,600
#define W2        (2*HWC/32)              // 129,600
#define W3        (2*HWC*GZ/32)           // 4,147,200
#define WT        (2*HWC*GT/32)           // 1,296,000
#define OFF2      0
#define OFF3      (W2)
#define OFFT      (W2+W3)
#define TOTW      (W2+W3+WT)              // 5,572,800

// scan tiles: 16384 words per 1024-thread block (16 words / thread)
#define TILE_W    16384
#define WPT       16
#define T2        ((W2+TILE_W-1)/TILE_W)  // 8
#define T3        ((W3+TILE_W-1)/TILE_W)  // 254
#define TT        ((WT+TILE_W-1)/TILE_W)  // 80
#define TOT_TILES (T2+T3+TT)              // 342

#define FLAG_AGG  (1ULL<<32)
#define FLAG_PRE  (2ULL<<32)

#define PTS       64                       // points per block in point role
#define LISTCAP   600064                   // >= 3 * N nonzero words

// ---------------- scratch (no cudaMalloc allowed) ----------------
// Invariants at entry to kernel_launch:
//   g_bm all-zero          (zero-init at load; emit role zeroes listed words)
//   g_ts/g_ticket/g_nnz    reset by k_mark (before this run's scan uses them)
// g_woff/g_bm2/g_list are written-before-read within each run.
__device__ unsigned g_bm[TOTW];
__device__ unsigned g_bm2[TOTW];
__device__ unsigned g_woff[TOTW];
__device__ uint2    g_list[LISTCAP];
__device__ unsigned long long g_ts[TOT_TILES];
__device__ unsigned g_ticket;
__device__ unsigned g_nnz;
__device__ unsigned g_cnt[3];

// ---------------- key computation ----------------
// XLA folds divide-by-constant into multiply-by-reciprocal (f32 RN folded).
__device__ __forceinline__ void keys_from_vals(float x, float y, float z, float t, int b,
                                               int& k2, int& k3, int& kt,
                                               int& ix, int& iy)
{
    ix = (int)(x * (1.0f/PP));
    iy = (int)(y * (1.0f/PP));
    int iz = (int)(z * (1.0f/VZ));
    int it = (int)(t * (1.0f/VT));
    int base = (b*HH + iy)*WW + ix;
    k2 = base;
    k3 = base*GZ + iz;
    kt = base*GT + it;
}

__device__ __forceinline__ void compute_keys(const float* __restrict__ xyzt,
                                             int i, int c0,
                                             int& k2, int& k3, int& kt,
                                             float& x, float& y, float& z, float& t,
                                             int& ix, int& iy)
{
    x = xyzt[(size_t)i*5+0];
    y = xyzt[(size_t)i*5+1];
    z = xyzt[(size_t)i*5+2];
    t = xyzt[(size_t)i*5+4];
    int b = (i < c0) ? 0 : 1;
    keys_from_vals(x, y, z, t, b, k2, k3, kt, ix, iy);
}

// ---------------- kernels ----------------
// mark: smem-staged coalesced loads + atomicOr; also resets scan/list state
// (safe: this run's scan/emit run strictly after; previous run's readers are
// separated by the kernel boundary).
__global__ __launch_bounds__(256) void k_mark(const float* __restrict__ xyzt,
                                              const int* __restrict__ cnt, int n)
{
    __shared__ __align__(16) float s[256*5];
    int blk0 = blockIdx.x*256;
    int gid  = blk0 + threadIdx.x;

    if (gid < TOT_TILES) g_ts[gid] = 0ULL;
    if (gid == 0) { g_ticket = 0u; g_nnz = 0u; }

    if (blk0 >= n) return;
    int npts = n - blk0; if (npts > 256) npts = 256;
    int nfl = npts*5;
    {   // blk0*5 floats = blockIdx*5120 bytes -> 16B aligned
        const float4* src4 = reinterpret_cast<const float4*>(xyzt + (size_t)blk0*5);
        int nf4 = nfl >> 2;
        float4* s4 = reinterpret_cast<float4*>(s);
        for (int u = threadIdx.x; u < nf4; u += 256) s4[u] = src4[u];
        for (int u = (nf4<<2) + threadIdx.x; u < nfl; u += 256)
            s[u] = xyzt[(size_t)blk0*5 + u];
    }
    __syncthreads();

    if (threadIdx.x < npts) {
        int c0 = cnt[0];
        float x = s[threadIdx.x*5+0];
        float y = s[threadIdx.x*5+1];
        float z = s[threadIdx.x*5+2];
        float t = s[threadIdx.x*5+4];
        int b = (gid < c0) ? 0 : 1;
        int k2, k3, kt, ix, iy;
        keys_from_vals(x, y, z, t, b, k2, k3, kt, ix, iy);
        atomicOr(&g_bm[OFF2 + (k2 >> 5)], 1u << (k2 & 31));
        atomicOr(&g_bm[OFF3 + (k3 >> 5)], 1u << (k3 & 31));
        atomicOr(&g_bm[OFFT + (kt >> 5)], 1u << (kt & 31));
    }
}

// Single-pass popcount scan with decoupled lookback. Also emits the
// compacted nonzero-word list and the g_bm2 snapshot used by the point role.
__global__ __launch_bounds__(1024) void k_scan()
{
    __shared__ unsigned s_warp[32];
    __shared__ unsigned s_total;
    __shared__ unsigned s_prefix;
    __shared__ unsigned s_tk;

    if (threadIdx.x == 0) s_tk = atomicAdd(&g_ticket, 1u);
    __syncthreads();
    unsigned tk = s_tk;

    int tile, secw0, words, stat0, secid, ntiles;
    if (tk < T2)           { tile = tk;           secw0 = OFF2; words = W2; stat0 = 0;     secid = 0; ntiles = T2; }
    else if (tk < T2+T3)   { tile = tk - T2;      secw0 = OFF3; words = W3; stat0 = T2;    secid = 1; ntiles = T3; }
    else                   { tile = tk - T2 - T3; secw0 = OFFT; words = WT; stat0 = T2+T3; secid = 2; ntiles = TT; }

    int tile_w0 = tile * TILE_W;
    int base_w  = tile_w0 + (int)threadIdx.x * WPT;

    unsigned bw[WPT];
    unsigned tsum = 0;
    #pragma unroll
    for (int q = 0; q < 4; q++) {
        int off = base_w + q*4;                     // section sizes are mod-4
        if (off < words) {
            uint4 v = *reinterpret_cast<const uint4*>(&g_bm[secw0 + off]);
            bw[q*4+0] = v.x; bw[q*4+1] = v.y; bw[q*4+2] = v.z; bw[q*4+3] = v.w;
        } else {
            bw[q*4+0] = bw[q*4+1] = bw[q*4+2] = bw[q*4+3] = 0u;
        }
        tsum += __popc(bw[q*4+0]) + __popc(bw[q*4+1]) + __popc(bw[q*4+2]) + __popc(bw[q*4+3]);
    }

    unsigned lane = threadIdx.x & 31, wid = threadIdx.x >> 5;
    unsigned incl = tsum;
    #pragma unroll
    for (int o = 1; o < 32; o <<= 1) {
        unsigned v = __shfl_up_sync(0xffffffffu, incl, o);
        if (lane >= (unsigned)o) incl += v;
    }
    if (lane == 31) s_warp[wid] = incl;
    __syncthreads();
    if (wid == 0) {
        unsigned v = s_warp[lane];
        unsigned si = v;
        #pragma unroll
        for (int o = 1; o < 32; o <<= 1) {
            unsigned tv = __shfl_up_sync(0xffffffffu, si, o);
            if (lane >= (unsigned)o) si += tv;
        }
        s_warp[lane] = si - v;
        if (lane == 31) s_total = si;
    }
    __syncthreads();
    unsigned texcl = incl - tsum + s_warp[wid];
    unsigned agg = s_total;

    if (wid == 0) {
        if (tile == 0) {
            if (lane == 0) {
                __threadfence();
                atomicExch(&g_ts[stat0], FLAG_PRE | (unsigned long long)agg);
                s_prefix = 0u;
            }
        } else {
            if (lane == 0) {
                __threadfence();
                atomicExch(&g_ts[stat0 + tile], FLAG_AGG | (unsigned long long)agg);
            }
            unsigned prefix = 0u;
            int idx = tile - 1;
            while (true) {
                int my = idx - (int)lane;
                unsigned long long st = (my >= 0)
                    ? atomicAdd(&g_ts[stat0 + my], 0ULL)
                    : FLAG_PRE;
                unsigned flag = (unsigned)(st >> 32);
                unsigned ready = __ballot_sync(0xffffffffu, flag != 0u);
                if (ready != 0xffffffffu) continue;
                unsigned preds = __ballot_sync(0xffffffffu, flag == 2u);
                if (preds) {
                    int fp = __ffs(preds) - 1;
                    unsigned val = (lane <= (unsigned)fp) ? (unsigned)st : 0u;
                    #pragma unroll
                    for (int o = 16; o > 0; o >>= 1)
                        val += __shfl_down_sync(0xffffffffu, val, o);
                    prefix += __shfl_sync(0xffffffffu, val, 0);
                    break;
                } else {
                    unsigned val = (my >= 0) ? (unsigned)st : 0u;
                    #pragma unroll
                    for (int o = 16; o > 0; o >>= 1)
                        val += __shfl_down_sync(0xffffffffu, val, o);
                    prefix += __shfl_sync(0xffffffffu, val, 0);
                    idx -= 32;
                }
            }
            if (lane == 0) {
                __threadfence();
                atomicExch(&g_ts[stat0 + tile],
                           FLAG_PRE | (unsigned long long)(prefix + agg));
                s_prefix = prefix;
            }
        }
    }
    __syncthreads();

    if (threadIdx.x == 0 && tile == ntiles - 1)
        g_cnt[secid] = s_prefix + s_total;

    // predicated per-word offsets + snapshot, and nonzero count
    unsigned run = s_prefix + texcl;
    unsigned mycnt = 0;
    #pragma unroll
    for (int j = 0; j < WPT; j++) {
        if (base_w + j < words && bw[j]) {
            g_woff[secw0 + base_w + j] = run;
            g_bm2[secw0 + base_w + j]  = bw[j];
            mycnt++;
        }
        run += __popc(bw[j]);
    }
    // warp-aggregated list append (order irrelevant; rank comes from g_woff)
    unsigned cincl = mycnt;
    #pragma unroll
    for (int o = 1; o < 32; o <<= 1) {
        unsigned v = __shfl_up_sync(0xffffffffu, cincl, o);
        if (lane >= (unsigned)o) cincl += v;
    }
    unsigned wtot = __shfl_sync(0xffffffffu, cincl, 31);
    unsigned lbase = 0;
    if (lane == 0 && wtot) lbase = atomicAdd(&g_nnz, wtot);
    lbase = __shfl_sync(0xffffffffu, lbase, 0);
    unsigned pos = lbase + cincl - mycnt;
    #pragma unroll
    for (int j = 0; j < WPT; j++) {
        if (base_w + j < words && bw[j]) {
            g_list[pos] = make_uint2((unsigned)(secw0 + base_w + j), bw[j]);
            pos++;
        }
    }
}

// ---------------- emit + tailfill role (list-driven) ----------------
__device__ __forceinline__ void emit_role(int eid, int NE, float* __restrict__ out, int n)
{
    int gid = eid*256 + (int)threadIdx.x;
    int stride = NE*256;

    // tail fill (invalid rows)
    {
        unsigned c2 = g_cnt[0], c3 = g_cnt[1], ct = g_cnt[2];
        int lenA = 3*n - 3*(int)c2;
        float* a = out + (size_t)3*c2;
        for (int j = gid; j < lenA; j += stride) a[j] = -1.0f;
        int lenB = 4*n - 4*(int)c3;
        float* b = out + (size_t)74*n + (size_t)4*c3;
        for (int j = gid; j < lenB; j += stride) b[j] = -1.0f;
        int lenC = 4*n - 4*(int)ct;
        float* c = out + (size_t)149*n + (size_t)4*ct;
        for (int j = gid; j < lenC; j += stride) c[j] = -1.0f;
    }

    size_t O_C3 = (size_t)74*n;
    size_t O_CT = (size_t)149*n;
    int nnz = (int)g_nnz;
    for (int e = gid; e < nnz; e += stride) {
        uint2 ent = g_list[e];
        int w = (int)ent.x;
        unsigned m = ent.y;
        g_bm[w] = 0u;                     // restore invariant (blind store)
        unsigned rank = g_woff[w];
        if (w < OFF3) {
            while (m) {
                int b = __ffs(m) - 1; m &= m - 1;
                int v = w*32 + b;
                int pb  = v / HWC;
                int rem = v % HWC;
                float* row = out + (size_t)rank*3;
                row[0] = (float)pb; row[1] = (float)(rem / WW); row[2] = (float)(rem % WW);
                rank++;
            }
        } else if (w < OFFT) {
            int wl = w - OFF3;
            while (m) {
                int b = __ffs(m) - 1; m &= m - 1;
                int v = wl*32 + b;
                int vb = v / (HWC*GZ);
                int r  = v % (HWC*GZ);
                int vy = r / (WW*GZ);
                r      = r % (WW*GZ);
                float* row = out + O_C3 + (size_t)rank*4;
                row[0] = (float)vb; row[1] = (float)(r % GZ); row[2] = (float)vy; row[3] = (float)(r / GZ);
                rank++;
            }
        } else {
            int wl = w - OFFT;
            while (m) {
                int b = __ffs(m) - 1; m &= m - 1;
                int v = wl*32 + b;
                int tb = v / (HWC*GT);
                int r  = v % (HWC*GT);
                int ty = r / (WW*GT);
                r      = r % (WW*GT);
                float* row = out + O_CT + (size_t)rank*4;
                row[0] = (float)tb; row[1] = (float)(r % GT); row[2] = (float)ty; row[3] = (float)(r / GT);
                rank++;
            }
        }
    }
}

// Fused third phase, interleaved 1:7 role split.
//   blockIdx % 8 == 0 -> emit/tailfill (eid = blockIdx/8 < NE)
//   else              -> point role, pid = blockIdx - blockIdx/8 - 1
// Point role reads ONLY the g_bm2 snapshot; emit writes ONLY g_bm -> no race.
__global__ __launch_bounds__(256, 8) void k_fused(const float* __restrict__ xyzt,
                                                  const int* __restrict__ cnt,
                                                  const float* __restrict__ pf,
                                                  float* __restrict__ out, int n, int NE)
{
    __shared__ __align__(16) float s_F[PTS*70];
    __shared__ float s_tv[PTS];     // t
    __shared__ float s_td[PTS];     // t - TZCENTER
    __shared__ int   s_k2[PTS], s_k3[PTS], s_kt[PTS];

    int b = blockIdx.x;
    if ((b & 7) == 0) {
        emit_role(b >> 3, NE, out, n);
        return;
    }
    int pid = b - (b >> 3) - 1;

    int i0 = pid * PTS;
    if (i0 >= n) return;
    int npts = n - i0; if (npts > PTS) npts = PTS;
    int tid = threadIdx.x;
    int c0 = cnt[0];

    // stage pf (vector loads, scalar smem stores)
    const float4* pf4 = reinterpret_cast<const float4*>(pf + (size_t)i0*CC);
    for (int u = tid; u < npts*(CC/4); u += 256) {
        float4 v = pf4[u];
        int p = u >> 4;
        int c = (u & 15) * 4;
        float* d = s_F + p*70 + c;
        d[0] = v.x; d[1] = v.y; d[2] = v.z; d[3] = v.w;
    }
    // geometry + keys
    if (tid < npts) {
        int i = i0 + tid;
        int k2, k3, kt, ix, iy; float x,y,z,t;
        compute_keys(xyzt, i, c0, k2, k3, kt, x, y, z, t, ix, iy);
        s_k2[tid] = k2; s_k3[tid] = k3; s_kt[tid] = kt;
        float cx = (ix + 0.5f) * PP;
        float cy = (iy + 0.5f) * PP;
        float* r = s_F + tid*70;
        r[64] = x; r[65] = y; r[66] = z;
        r[67] = x - cx; r[68] = y - cy; r[69] = z - ZCENTER;
        s_tv[tid] = t; s_td[tid] = t - TZCENTER;
    }
    __syncthreads();

    // three rank lookups per point (reads the stable g_bm2 snapshot)
    if (tid < 3*npts) {
        int sec = (tid < npts) ? 0 : (tid < 2*npts ? 1 : 2);
        int p = tid - sec*npts;
        int k   = (sec == 0) ? s_k2[p] : (sec == 1) ? s_k3[p] : s_kt[p];
        int off = (sec == 0) ? OFF2 : (sec == 1) ? OFF3 : OFFT;
        size_t dst = (sec == 0) ? (size_t)3*n : (sec == 1) ? (size_t)78*n : (size_t)153*n;
        int w = k >> 5, bb = k & 31;
        unsigned inv = g_woff[off + w] + (unsigned)__popc(g_bm2[off + w] & ((1u << bb) - 1u));
        out[dst + i0 + p] = (float)inv;
    }

    int E = npts*70;
    float* fb = out + (size_t)4*n   + (size_t)i0*70;
    float* zb = out + (size_t)79*n  + (size_t)i0*70;
    float* tb = out + (size_t)154*n + (size_t)i0*70;

    if ((n & 3) == 0) {   // all bases 16B-aligned
        const float4* s4 = reinterpret_cast<const float4*>(s_F);
        float4* f4 = reinterpret_cast<float4*>(fb);
        float4* z4 = reinterpret_cast<float4*>(zb);
        float4* t4 = reinterpret_cast<float4*>(tb);
        int E4 = E >> 2;
        for (int u = tid; u < E4; u += 256) {
            float4 v = s4[u];
            f4[u] = v;
            z4[u] = v;
            int e = u << 2;
            int p = e / 70;
            int r = e - p*70;
            if (r == 64)      { v.z = s_tv[p]; }
            else if (r == 66) { v.x = s_tv[p]; v.w = s_td[p]; }
            else if (r == 68) { v.y = s_td[p]; }
            t4[u] = v;
        }
        int rem = E & 3;   // 0 or 2 (70*npts)
        if (rem && tid == 0) {
            int e = E - 2;
            float v0 = s_F[e], v1 = s_F[e+1];
            fb[e] = v0; fb[e+1] = v1;
            zb[e] = v0; zb[e+1] = v1;
            tb[e] = v0; tb[e+1] = s_td[npts-1];
        }
    } else {               // generic scalar fallback
        for (int e = tid; e < E; e += 256) {
            float v = s_F[e];
            fb[e] = v;
            zb[e] = v;
            int p = e / 70;
            int r = e - p*70;
            float vt = (r == 66) ? s_tv[p] : (r == 69) ? s_td[p] : v;
            tb[e] = vt;
        }
    }
}

// ---------------- launch ----------------
extern "C" void kernel_launch(void* const* d_in, const int* in_sizes, int n_in,
                              void* d_out, int out_size)
{
    const float* xyzt = (const float*)d_in[0];
    const int*   cnt  = (const int*)d_in[1];
    const float* pf   = (const float*)d_in[2];
    float*       out  = (float*)d_out;
    int n = in_sizes[0] / 5;

    // 1) mark occupied bins (+ reset scan/list state)
    {
        int nb = (n + 255)/256;
        int need = (TOT_TILES + 255)/256;
        if (nb < need) nb = need;
        k_mark<<<nb, 256>>>(xyzt, cnt, n);
    }
    // 2) single-pass popcount scan (+ snapshot, nonzero-word list, totals)
    k_scan<<<TOT_TILES, 1024>>>();
    // 3) fused: point features + list-driven emit + tailfill
    {
        int NP = (n + PTS - 1)/PTS;
        int NE = (NP + 6)/7;
        k_fused<<<NP + NE, 256>>>(xyzt, cnt, pf, out, n, NE);
    }
}